// round 2
// baseline (speedup 1.0000x reference)
#include <cuda_runtime.h>
#include <math.h>

#define NB   16
#define CIN  64
#define CE   64
#define HIN  256
#define HOUT 128

// ---------------- device-global scratch (no allocations allowed) ----------------
__device__ float g_pooled[NB * CIN];
__device__ int   g_sel_idx[NB * 2];
__device__ float g_sel_w[NB * 2];

// ---------------- kernel 1: global average pool per (b, c) ----------------
__global__ void pool_kernel(const float* __restrict__ x) {
    int bc = blockIdx.x;  // b*CIN + c
    const float4* p = (const float4*)(x + (size_t)bc * (HIN * HIN));
    float s = 0.f;
    for (int i = threadIdx.x; i < (HIN * HIN) / 4; i += 256) {
        float4 v = p[i];
        s += (v.x + v.y) + (v.z + v.w);
    }
    __shared__ float red[8];
    for (int o = 16; o; o >>= 1) s += __shfl_xor_sync(0xffffffffu, s, o);
    if ((threadIdx.x & 31) == 0) red[threadIdx.x >> 5] = s;
    __syncthreads();
    if (threadIdx.x < 8) {
        s = red[threadIdx.x];
        for (int o = 4; o; o >>= 1) s += __shfl_xor_sync(0xffu, s, o);
        if (threadIdx.x == 0) g_pooled[bc] = s * (1.f / (HIN * HIN));
    }
}

// ---------------- kernel 2: gate (linear -> softmax -> top2 renorm) ----------------
__global__ void gate_kernel(const float* __restrict__ gw, const float* __restrict__ gb) {
    int b = threadIdx.x;
    if (b >= NB) return;
    float logits[4];
    for (int e = 0; e < 4; e++) {
        float s = gb[e];
        for (int c = 0; c < CIN; c++) s += g_pooled[b * CIN + c] * gw[e * CIN + c];
        logits[e] = s;
    }
    float mx = logits[0];
    for (int e = 1; e < 4; e++) mx = fmaxf(mx, logits[e]);
    float g[4], sum = 0.f;
    for (int e = 0; e < 4; e++) { g[e] = expf(logits[e] - mx); sum += g[e]; }
    for (int e = 0; e < 4; e++) g[e] /= sum;
    // top-2, ties resolved to lower index (matches lax.top_k)
    int i0 = 0;
    for (int e = 1; e < 4; e++) if (g[e] > g[i0]) i0 = e;
    int i1 = -1;
    for (int e = 0; e < 4; e++) {
        if (e == i0) continue;
        if (i1 < 0 || g[e] > g[i1]) i1 = e;
    }
    float den = g[i0] + g[i1] + 1e-8f;
    g_sel_idx[b * 2 + 0] = i0; g_sel_w[b * 2 + 0] = g[i0] / den;
    g_sel_idx[b * 2 + 1] = i1; g_sel_w[b * 2 + 1] = g[i1] / den;
}

// ---------------- kernel 3: fused conv + bias + BN + GELU + slot weight ----------------
// One instantiation per expert (compile-time K, D). Blocks early-exit unless
// their (b, slot) selected expert E. Block tile: 32x16 output pixels, 256
// threads; each thread computes 2 pixels (rows oy, oy+8) x 16 output channels
// (co-group in gridDim.z) = 32 accumulators.
template <int K, int D, int E>
__global__ __launch_bounds__(256)
void conv_kernel(const float* __restrict__ x, const float* __restrict__ w,
                 const float* __restrict__ cb,
                 const float* __restrict__ bn_scale, const float* __restrict__ bn_bias,
                 const float* __restrict__ bn_mean,  const float* __restrict__ bn_var,
                 float* __restrict__ out) {
    constexpr int PAD = D * (K - 1) / 2;
    constexpr int PW  = 63 + (K - 1) * D;   // input patch width  (32 out px * 2 + halo)
    constexpr int PH  = 31 + (K - 1) * D;   // input patch height (16 out px * 2 + halo)

    const int z   = blockIdx.z;
    const int cog = z & 3;
    const int s   = (z >> 2) & 1;
    const int b   = z >> 3;

    if (g_sel_idx[b * 2 + s] != E) return;  // uniform per block

    __shared__ float patch[PH * PW];
    __shared__ __align__(16) float wsm[K * K * 16];

    const int tid = threadIdx.x;
    const int tx  = tid & 31;
    const int ty  = tid >> 5;
    const int oy  = blockIdx.y * 16 + ty;   // second pixel at oy + 8
    const int ox  = blockIdx.x * 32 + tx;
    const int iy0 = blockIdx.y * 32 - PAD;
    const int ix0 = blockIdx.x * 64 - PAD;

    float acc0[16], acc1[16];
#pragma unroll
    for (int c = 0; c < 16; c++) { acc0[c] = 0.f; acc1[c] = 0.f; }

    for (int cin = 0; cin < CIN; cin++) {
        __syncthreads();
        // stage input patch (zero-padded)
        const float* xb = x + ((size_t)(b * CIN + cin)) * (HIN * HIN);
        for (int i = tid; i < PH * PW; i += 256) {
            int r = i / PW, q = i - r * PW;        // PW is constexpr
            int gy = iy0 + r, gx = ix0 + q;
            float v = 0.f;
            if ((unsigned)gy < (unsigned)HIN && (unsigned)gx < (unsigned)HIN)
                v = __ldg(xb + gy * HIN + gx);
            patch[i] = v;
        }
        // stage weights for this cin: layout wsm[tap][c], c = co within group
        const float* wb = w + cin * (K * K);
        for (int i = tid; i < K * K * 16; i += 256) {
            int t = i >> 4, c = i & 15;
            wsm[i] = __ldg(wb + (size_t)(cog * 16 + c) * (CIN * K * K) + t);
        }
        __syncthreads();

        const float* pb0 = patch + (ty * 2) * PW + tx * 2;        // pixel row oy
        const float* pb1 = pb0 + 16 * PW;                         // pixel row oy+8
#pragma unroll 1
        for (int kh = 0; kh < K; kh++) {
            const float*  pr0 = pb0 + kh * D * PW;
            const float*  pr1 = pb1 + kh * D * PW;
            const float4* wr  = ((const float4*)wsm) + kh * K * 4;
#pragma unroll
            for (int kw = 0; kw < K; kw++) {
                float  xv0 = pr0[kw * D];
                float  xv1 = pr1[kw * D];
                float4 wv0 = wr[kw * 4 + 0];
                float4 wv1 = wr[kw * 4 + 1];
                float4 wv2 = wr[kw * 4 + 2];
                float4 wv3 = wr[kw * 4 + 3];
                acc0[0]  = fmaf(xv0, wv0.x, acc0[0]);   acc1[0]  = fmaf(xv1, wv0.x, acc1[0]);
                acc0[1]  = fmaf(xv0, wv0.y, acc0[1]);   acc1[1]  = fmaf(xv1, wv0.y, acc1[1]);
                acc0[2]  = fmaf(xv0, wv0.z, acc0[2]);   acc1[2]  = fmaf(xv1, wv0.z, acc1[2]);
                acc0[3]  = fmaf(xv0, wv0.w, acc0[3]);   acc1[3]  = fmaf(xv1, wv0.w, acc1[3]);
                acc0[4]  = fmaf(xv0, wv1.x, acc0[4]);   acc1[4]  = fmaf(xv1, wv1.x, acc1[4]);
                acc0[5]  = fmaf(xv0, wv1.y, acc0[5]);   acc1[5]  = fmaf(xv1, wv1.y, acc1[5]);
                acc0[6]  = fmaf(xv0, wv1.z, acc0[6]);   acc1[6]  = fmaf(xv1, wv1.z, acc1[6]);
                acc0[7]  = fmaf(xv0, wv1.w, acc0[7]);   acc1[7]  = fmaf(xv1, wv1.w, acc1[7]);
                acc0[8]  = fmaf(xv0, wv2.x, acc0[8]);   acc1[8]  = fmaf(xv1, wv2.x, acc1[8]);
                acc0[9]  = fmaf(xv0, wv2.y, acc0[9]);   acc1[9]  = fmaf(xv1, wv2.y, acc1[9]);
                acc0[10] = fmaf(xv0, wv2.z, acc0[10]);  acc1[10] = fmaf(xv1, wv2.z, acc1[10]);
                acc0[11] = fmaf(xv0, wv2.w, acc0[11]);  acc1[11] = fmaf(xv1, wv2.w, acc1[11]);
                acc0[12] = fmaf(xv0, wv3.x, acc0[12]);  acc1[12] = fmaf(xv1, wv3.x, acc1[12]);
                acc0[13] = fmaf(xv0, wv3.y, acc0[13]);  acc1[13] = fmaf(xv1, wv3.y, acc1[13]);
                acc0[14] = fmaf(xv0, wv3.z, acc0[14]);  acc1[14] = fmaf(xv1, wv3.z, acc1[14]);
                acc0[15] = fmaf(xv0, wv3.w, acc0[15]);  acc1[15] = fmaf(xv1, wv3.w, acc1[15]);
            }
        }
    }

    // epilogue: bias + BN + exact GELU + slot weight
    const float sw = g_sel_w[b * 2 + s];
#pragma unroll
    for (int c = 0; c < 16; c++) {
        int   co   = cog * 16 + c;
        float inv  = bn_scale[E * CE + co] * rsqrtf(bn_var[E * CE + co] + 1e-5f);
        float beta = bn_bias[E * CE + co] - bn_mean[E * CE + co] * inv;
        float bc   = cb[co];
        size_t base = ((size_t)(b * 128 + s * 64 + co)) * (HOUT * HOUT) + ox;

        float y0   = (acc0[c] + bc) * inv + beta;
        float g0   = 0.5f * y0 * (1.f + erff(y0 * 0.70710678118654752f));
        out[base + (size_t)oy * HOUT] = g0 * sw;

        float y1   = (acc1[c] + bc) * inv + beta;
        float g1   = 0.5f * y1 * (1.f + erff(y1 * 0.70710678118654752f));
        out[base + (size_t)(oy + 8) * HOUT] = g1 * sw;
    }
}

// ---------------- launch ----------------
extern "C" void kernel_launch(void* const* d_in, const int* in_sizes, int n_in,
                              void* d_out, int out_size) {
    const float* x   = (const float*)d_in[0];
    const float* w0  = (const float*)d_in[1];
    const float* b0  = (const float*)d_in[2];
    const float* w1  = (const float*)d_in[3];
    const float* b1  = (const float*)d_in[4];
    const float* w2  = (const float*)d_in[5];
    const float* b2  = (const float*)d_in[6];
    const float* w3  = (const float*)d_in[7];
    const float* b3  = (const float*)d_in[8];
    const float* bns = (const float*)d_in[9];
    const float* bnb = (const float*)d_in[10];
    const float* bnm = (const float*)d_in[11];
    const float* bnv = (const float*)d_in[12];
    const float* gw  = (const float*)d_in[13];
    const float* gb  = (const float*)d_in[14];
    float* out = (float*)d_out;

    pool_kernel<<<NB * CIN, 256>>>(x);
    gate_kernel<<<1, 32>>>(gw, gb);

    // grid: x = 128/32 tiles, y = 128/16 tiles, z = (b slowest) * slot * co-group
    dim3 grid(HOUT / 32, HOUT / 16, NB * 2 * 4);
    conv_kernel<3, 1, 0><<<grid, 256>>>(x, w0, b0, bns, bnb, bnm, bnv, out);
    conv_kernel<5, 2, 1><<<grid, 256>>>(x, w1, b1, bns, bnb, bnm, bnv, out);
    conv_kernel<7, 3, 2><<<grid, 256>>>(x, w2, b2, bns, bnb, bnm, bnv, out);
    conv_kernel<9, 4, 3><<<grid, 256>>>(x, w3, b3, bns, bnb, bnm, bnv, out);
}